// round 17
// baseline (speedup 1.0000x reference)
#include <cuda_runtime.h>
#include <cuda_fp16.h>
#include <mma.h>
#include <math.h>
#include <cstdint>

using namespace nvcuda;

// Problem constants (fixed by the dataset)
#define NN 100000      // nodes
#define NPAD 100096    // NN rounded to 128
#define NE 1600000     // edges
#define FIN 394        // input features
#define FKP 416        // FIN padded to multiple of 32 (W1 rows; pads stay zero)
#define FH  256        // hidden features
#define FO  64         // output features
#define NSCAN_BLKS ((NN + 1023) / 1024)

// ---------------- scratch (device globals; no allocation allowed) ----------
__device__ float  g_deg [NN];
__device__ float  g_dinv[NN];
__device__ int    g_cnt [NN];
__device__ int    g_rowptr[NN + 1];
__device__ int    g_bsum[NSCAN_BLKS];
__device__ int    g_esrc[NE];
__device__ float  g_enorm[NE];
__device__ __half g_w1h[FKP * FH];                    // W1 fp16 (padded rows zero)
__device__ __half g_w2h[FH * FO],  g_w2l[FH * FO];    // W2 fp16 hi/lo
__device__ __half g_xw1h[(size_t)NPAD * FH];          // x @ W1, fp16
__device__ __half g_h   [(size_t)NPAD * FH];          // relu(agg1+self+b1), fp16
__device__ __half g_hw2h[(size_t)NPAD * FO];          // h @ W2, fp16

// ---------------- cp.async helpers -------------------------------------------
__device__ __forceinline__ void cpa16(void* dst, const void* src) {
    uint32_t d = (uint32_t)__cvta_generic_to_shared(dst);
    asm volatile("cp.async.cg.shared.global [%0], [%1], 16;" :: "r"(d), "l"(src));
}
#define CP_COMMIT() asm volatile("cp.async.commit_group;")
#define CP_WAIT1()  asm volatile("cp.async.wait_group 1;")
#define CP_WAIT0()  asm volatile("cp.async.wait_group 0;")

// ---------------- weight convert kernel (W1 -> fp16, W2 -> fp16 hi/lo) ------
__global__ void splitw_kernel(const float* __restrict__ W1,
                              const float* __restrict__ W2) {
    int i = blockIdx.x * blockDim.x + threadIdx.x;
    if (i < FIN * FH) {
        g_w1h[i] = __float2half_rn(W1[i]);    // rows [FIN..FKP) stay BSS-zero
    } else if (i < FIN * FH + FH * FO) {
        int j = i - FIN * FH;
        float v = W2[j];
        __half hi = __float2half_rn(v);
        g_w2h[j] = hi;
        g_w2l[j] = __float2half_rn(v - __half2float(hi));
    }
}

// ---------------- small prep kernels ----------------------------------------
__global__ void z1_kernel() {
    int i = blockIdx.x * blockDim.x + threadIdx.x;
    if (i < NN) { g_cnt[i] = 0; g_deg[i] = 1.0f; }
}

__global__ void hist_kernel(const int* __restrict__ ei, const float* __restrict__ ew) {
    int e = blockIdx.x * blockDim.x + threadIdx.x;
    if (e < NE) {
        int dst = ei[NE + e];
        atomicAdd(&g_cnt[dst], 1);
        atomicAdd(&g_deg[dst], ew[e]);
    }
}

__global__ void dinv_kernel() {
    int i = blockIdx.x * blockDim.x + threadIdx.x;
    if (i < NN) {
        float d = g_deg[i];
        g_dinv[i] = (d > 0.f) ? rsqrtf(d) : 0.f;
    }
}

// ---------------- prefix scan over g_cnt -> g_rowptr ------------------------
__global__ void scan1_kernel() {
    __shared__ int s[1024];
    int tid = threadIdx.x;
    int gi = blockIdx.x * 1024 + tid;
    int v = (gi < NN) ? g_cnt[gi] : 0;
    s[tid] = v;
    __syncthreads();
#pragma unroll
    for (int off = 1; off < 1024; off <<= 1) {
        int t = (tid >= off) ? s[tid - off] : 0;
        __syncthreads();
        s[tid] += t;
        __syncthreads();
    }
    if (gi < NN) g_rowptr[gi] = s[tid] - v;
    if (tid == 1023) g_bsum[blockIdx.x] = s[1023];
}

__global__ void scan2_kernel() {
    __shared__ int s[128];
    int tid = threadIdx.x;
    int v = (tid < NSCAN_BLKS) ? g_bsum[tid] : 0;
    s[tid] = v;
    __syncthreads();
#pragma unroll
    for (int off = 1; off < 128; off <<= 1) {
        int t = (tid >= off) ? s[tid - off] : 0;
        __syncthreads();
        s[tid] += t;
        __syncthreads();
    }
    if (tid < NSCAN_BLKS) g_bsum[tid] = s[tid] - v;
}

__global__ void scan3_kernel() {
    int gi = blockIdx.x * 1024 + threadIdx.x;
    if (gi < NN) {
        g_rowptr[gi] += g_bsum[blockIdx.x];
        g_cnt[gi] = 0;
    }
    if (gi == 0) g_rowptr[NN] = NE;
}

__global__ void scatter_kernel(const int* __restrict__ ei, const float* __restrict__ ew) {
    int e = blockIdx.x * blockDim.x + threadIdx.x;
    if (e < NE) {
        int src = ei[e];
        int dst = ei[NE + e];
        int p = g_rowptr[dst] + atomicAdd(&g_cnt[dst], 1);
        g_esrc[p]  = src;
        g_enorm[p] = g_dinv[src] * ew[e] * g_dinv[dst];
    }
}

// ---------------- pack helper ------------------------------------------------
__device__ __forceinline__ uint4 pack8(float4 a, float4 b) {
    __half2 h0 = __floats2half2_rn(a.x, a.y);
    __half2 h1 = __floats2half2_rn(a.z, a.w);
    __half2 h2 = __floats2half2_rn(b.x, b.y);
    __half2 h3 = __floats2half2_rn(b.z, b.w);
    uint4 r;
    r.x = *(unsigned*)&h0; r.y = *(unsigned*)&h1;
    r.z = *(unsigned*)&h2; r.w = *(unsigned*)&h3;
    return r;
}

// =============================================================================
// GEMM1: xw1h = x(fp32, converted in-kernel) @ W1(fp16) — single-term
// BM=128, BN=64, BK=32, 256 threads (8 warps 4x2), 2 CTAs/SM.
// A: per-tile LDG.64 fp32 -> regs -> convert -> fp16 smem (double-buffered).
// B: cp.async fp16 (double-buffered).
// dynamic smem (halves): Ah[2][128][40], B[2][32][72]
// =============================================================================
#define G1_OA  0
#define G1_OB  10240
#define G1_AST 5120                          // stage stride A (halves)
#define G1_BST 2304                          // stage stride B (halves)
#define G1_SMEM_BYTES 29696                  // 14848 halves
#define G1_NIT (FKP / 32)                    // 13

__global__ void __launch_bounds__(256, 2)
gemm1_kernel(const float* __restrict__ Ag, const __half* __restrict__ Bg,
             __half* __restrict__ Out) {
    extern __shared__ __align__(16) __half smem[];
    const int tid = threadIdx.x;
    const int wid = tid >> 5;
    const int wm = wid >> 1;                 // 0..3
    const int wn = wid & 1;                  // 0..1
    const int row0 = blockIdx.y * 128;
    const int col0 = blockIdx.x * 64;

    // A mapping: 2 threads per row, 16 consecutive floats each
    const int arow = tid >> 1, apart = tid & 1;
    const int gm = row0 + arow;
    const bool rowok = gm < NN;
    const float* aRow = Ag + (size_t)gm * FIN + apart * 16;
    __half* aDstBase = smem + G1_OA + arow * 40 + apart * 16;

    // B mapping: one 16B chunk per thread
    const int bkr = tid >> 3, bcp = tid & 7;
    const __half* bSrc = Bg + (size_t)bkr * FH + col0 + bcp * 8;
    __half* bDst = smem + G1_OB + bkr * 72 + bcp * 8;

    float av[16];
    auto load_a = [&](int it) {
        int gkb = it * 32 + apart * 16;
#pragma unroll
        for (int q = 0; q < 8; q++) {
            int gk = gkb + q * 2;
            float2 v = make_float2(0.f, 0.f);
            if (rowok && gk < FIN) v = *(const float2*)&aRow[it * 32 + q * 2];
            av[q * 2] = v.x; av[q * 2 + 1] = v.y;
        }
    };
    auto store_a = [&](int st) {
        __half2 h[8];
#pragma unroll
        for (int q = 0; q < 8; q++) h[q] = __floats2half2_rn(av[q * 2], av[q * 2 + 1]);
        uint4 u0, u1;
        u0.x = *(unsigned*)&h[0]; u0.y = *(unsigned*)&h[1];
        u0.z = *(unsigned*)&h[2]; u0.w = *(unsigned*)&h[3];
        u1.x = *(unsigned*)&h[4]; u1.y = *(unsigned*)&h[5];
        u1.z = *(unsigned*)&h[6]; u1.w = *(unsigned*)&h[7];
        *(uint4*)(aDstBase + st * G1_AST)     = u0;
        *(uint4*)(aDstBase + st * G1_AST + 8) = u1;
    };

    wmma::fragment<wmma::accumulator, 16, 16, 16, float> c[2][2];
#pragma unroll
    for (int i = 0; i < 2; i++)
#pragma unroll
        for (int j = 0; j < 2; j++) wmma::fill_fragment(c[i][j], 0.0f);

    // prologue: A(0) regs, B(0) cp.async
    load_a(0);
    cpa16(bDst, bSrc);
    CP_COMMIT();

    for (int it = 0; it < G1_NIT; it++) {
        int s = it & 1;
        store_a(s);                           // convert A(it) regs -> smem
        CP_WAIT0();                           // B(it) arrived
        __syncthreads();

        if (it + 1 < G1_NIT) {
            load_a(it + 1);                   // LDG latency hides under MMAs
            cpa16(bDst + ((it + 1) & 1) * G1_BST, bSrc + (size_t)(it + 1) * 32 * FH);
            CP_COMMIT();
        }

        const __half* pA = smem + G1_OA + s * G1_AST + (wm * 32) * 40;
        const __half* pB = smem + G1_OB + s * G1_BST + wn * 32;
#pragma unroll
        for (int sub = 0; sub < 2; sub++) {
            wmma::fragment<wmma::matrix_a, 16, 16, 16, __half, wmma::row_major> a[2];
            wmma::fragment<wmma::matrix_b, 16, 16, 16, __half, wmma::row_major> b[2];
#pragma unroll
            for (int i = 0; i < 2; i++)
                wmma::load_matrix_sync(a[i], pA + i * 16 * 40 + sub * 16, 40);
#pragma unroll
            for (int j = 0; j < 2; j++)
                wmma::load_matrix_sync(b[j], pB + (sub * 16) * 72 + j * 16, 72);
#pragma unroll
            for (int i = 0; i < 2; i++)
#pragma unroll
                for (int j = 0; j < 2; j++)
                    wmma::mma_sync(c[i][j], a[i], b[j], c[i][j]);
        }
        __syncthreads();
    }

    // epilogue: two 64-row passes via smem staging (stride 68 floats)
    float* C = (float*)smem;
#pragma unroll
    for (int p = 0; p < 2; p++) {
        if (p) __syncthreads();
        if ((wm >> 1) == p) {
#pragma unroll
            for (int i = 0; i < 2; i++)
#pragma unroll
                for (int j = 0; j < 2; j++)
                    wmma::store_matrix_sync(&C[((wm & 1) * 32 + i * 16) * 68 + wn * 32 + j * 16],
                                            c[i][j], 68, wmma::mem_row_major);
        }
        __syncthreads();
#pragma unroll
        for (int uu = 0; uu < 2; uu++) {
            int chunk = tid + uu * 256;
            int r = chunk >> 3, col = (chunk & 7) * 8;
            float4 a = *(float4*)&C[r * 68 + col];
            float4 b = *(float4*)&C[r * 68 + col + 4];
            *(uint4*)&Out[(size_t)(row0 + p * 64 + r) * FH + col0 + col] = pack8(a, b);
        }
    }
}

// =============================================================================
// GEMM2: hw2h = h(fp16 exact) @ W2, 2-term (ABh + ABl)
// BM=128, BN=64, BK=16, 256 threads (8 warps 4x2), 2-stage cp.async
// =============================================================================
#define G2_OA  0
#define G2_OBH (2 * 128 * 24)
#define G2_OBL (G2_OBH + 2 * 16 * 72)
#define G2_TOT (G2_OBL + 2 * 16 * 72)
#define G2_AST (128 * 24)
#define G2_BST (16 * 72)
#define G2_NIT (FH / 16)                     // 16

__global__ void __launch_bounds__(256, 2)
gemm2_kernel(const __half* __restrict__ Ag, const __half* __restrict__ Bhg,
             const __half* __restrict__ Blg, __half* __restrict__ Out) {
    __shared__ alignas(16) __half smem[G2_TOT];
    const int tid = threadIdx.x;
    const int wid = tid >> 5;
    const int wm = wid >> 1;
    const int wn = wid & 1;
    const int row0 = blockIdx.y * 128;

    const int am = tid >> 1, apart = tid & 1;
    const int ub = tid & 127;
    const bool blo = tid >= 128;
    const int bk = ub >> 3, bc8 = ub & 7;
    const __half* aSrc = Ag + (size_t)(row0 + am) * FH + apart * 8;
    const __half* bSrc = (blo ? Blg : Bhg) + (size_t)bk * FO + bc8 * 8;
    __half* aDst = smem + G2_OA + am * 24 + apart * 8;
    __half* bDst = smem + (blo ? G2_OBL : G2_OBH) + bk * 72 + bc8 * 8;

    wmma::fragment<wmma::accumulator, 16, 16, 16, float> c[2][2];
#pragma unroll
    for (int i = 0; i < 2; i++)
#pragma unroll
        for (int j = 0; j < 2; j++) wmma::fill_fragment(c[i][j], 0.0f);

    cpa16(aDst, aSrc);
    cpa16(bDst, bSrc);
    CP_COMMIT();

    for (int it = 0; it < G2_NIT; it++) {
        if (it + 1 < G2_NIT) {
            int st = (it + 1) & 1;
            cpa16(aDst + st * G2_AST, aSrc + (it + 1) * 16);
            cpa16(bDst + st * G2_BST, bSrc + (size_t)(it + 1) * 16 * FO);
            CP_COMMIT();
            CP_WAIT1();
        } else {
            CP_WAIT0();
        }
        __syncthreads();

        int s = it & 1;
        const __half* pA  = smem + G2_OA  + s * G2_AST + (wm * 32) * 24;
        const __half* pBh = smem + G2_OBH + s * G2_BST + wn * 32;
        const __half* pBl = smem + G2_OBL + s * G2_BST + wn * 32;

        wmma::fragment<wmma::matrix_a, 16, 16, 16, __half, wmma::row_major> a[2];
        wmma::fragment<wmma::matrix_b, 16, 16, 16, __half, wmma::row_major> bh[2], bl[2];
#pragma unroll
        for (int i = 0; i < 2; i++)
            wmma::load_matrix_sync(a[i], pA + i * 16 * 24, 24);
#pragma unroll
        for (int j = 0; j < 2; j++) {
            wmma::load_matrix_sync(bh[j], pBh + j * 16, 72);
            wmma::load_matrix_sync(bl[j], pBl + j * 16, 72);
        }
#pragma unroll
        for (int i = 0; i < 2; i++)
#pragma unroll
            for (int j = 0; j < 2; j++) {
                wmma::mma_sync(c[i][j], a[i], bh[j], c[i][j]);
                wmma::mma_sync(c[i][j], a[i], bl[j], c[i][j]);
            }
        __syncthreads();
    }

    float* C = (float*)smem;
#pragma unroll
    for (int p = 0; p < 2; p++) {
        if (p) __syncthreads();
        if ((wm >> 1) == p) {
#pragma unroll
            for (int i = 0; i < 2; i++)
#pragma unroll
                for (int j = 0; j < 2; j++)
                    wmma::store_matrix_sync(&C[((wm & 1) * 32 + i * 16) * 68 + wn * 32 + j * 16],
                                            c[i][j], 68, wmma::mem_row_major);
        }
        __syncthreads();
#pragma unroll
        for (int uu = 0; uu < 2; uu++) {
            int chunk = tid + uu * 256;
            int r = chunk >> 3, col = (chunk & 7) * 8;
            float4 a = *(float4*)&C[r * 68 + col];
            float4 b = *(float4*)&C[r * 68 + col + 4];
            *(uint4*)&Out[(size_t)(row0 + p * 64 + r) * FO + col] = pack8(a, b);
        }
    }
}

// ---------------- fp16 gather helpers ----------------------------------------
__device__ __forceinline__ void fma8(float acc[8], uint4 r, float n) {
    __half2* h = (__half2*)&r;
#pragma unroll
    for (int q = 0; q < 4; q++) {
        float2 p = __half22float2(h[q]);
        acc[q * 2]     = fmaf(n, p.x, acc[q * 2]);
        acc[q * 2 + 1] = fmaf(n, p.y, acc[q * 2 + 1]);
    }
}

// ---------------- layer-1 gather: h = relu(agg + self + b1), fp16 out -------
__global__ void agg1_kernel(const float4* __restrict__ b1v) {
    int d = blockIdx.x * 8 + threadIdx.y;
    if (d >= NN) return;
    int f = threadIdx.x;                          // 0..31
    const uint4* X = (const uint4*)g_xw1h;
    float di = g_dinv[d];
    float s = di * di;
    float acc[8];
    {
        uint4 r = X[(size_t)d * 32 + f];
        __half2* h = (__half2*)&r;
#pragma unroll
        for (int q = 0; q < 4; q++) {
            float2 p = __half22float2(h[q]);
            acc[q * 2]     = s * p.x;
            acc[q * 2 + 1] = s * p.y;
        }
    }
    int beg = g_rowptr[d], end = g_rowptr[d + 1];
    int j = beg;
    for (; j + 3 < end; j += 4) {
        int s0 = g_esrc[j], s1 = g_esrc[j + 1], s2 = g_esrc[j + 2], s3 = g_esrc[j + 3];
        float n0 = g_enorm[j], n1 = g_enorm[j + 1], n2 = g_enorm[j + 2], n3 = g_enorm[j + 3];
        uint4 r0 = X[(size_t)s0 * 32 + f];
        uint4 r1 = X[(size_t)s1 * 32 + f];
        uint4 r2 = X[(size_t)s2 * 32 + f];
        uint4 r3 = X[(size_t)s3 * 32 + f];
        fma8(acc, r0, n0); fma8(acc, r1, n1); fma8(acc, r2, n2); fma8(acc, r3, n3);
    }
    for (; j < end; j++) {
        fma8(acc, X[(size_t)g_esrc[j] * 32 + f], g_enorm[j]);
    }
    float4 b0 = b1v[f * 2], b1 = b1v[f * 2 + 1];
    float4 o0, o1;
    o0.x = fmaxf(acc[0] + b0.x, 0.f); o0.y = fmaxf(acc[1] + b0.y, 0.f);
    o0.z = fmaxf(acc[2] + b0.z, 0.f); o0.w = fmaxf(acc[3] + b0.w, 0.f);
    o1.x = fmaxf(acc[4] + b1.x, 0.f); o1.y = fmaxf(acc[5] + b1.y, 0.f);
    o1.z = fmaxf(acc[6] + b1.z, 0.f); o1.w = fmaxf(acc[7] + b1.w, 0.f);
    ((uint4*)g_h)[(size_t)d * 32 + f] = pack8(o0, o1);
}

// ---------------- layer-2 gather -> out (fp32) -------------------------------
__global__ void agg2_kernel(const float4* __restrict__ b2v, float4* __restrict__ out) {
    int d = blockIdx.x * 32 + threadIdx.y;
    if (d >= NN) return;
    int f = threadIdx.x;                          // 0..7
    const uint4* X = (const uint4*)g_hw2h;
    float di = g_dinv[d];
    float s = di * di;
    float acc[8];
    {
        uint4 r = X[(size_t)d * 8 + f];
        __half2* h = (__half2*)&r;
#pragma unroll
        for (int q = 0; q < 4; q++) {
            float2 p = __half22float2(h[q]);
            acc[q * 2]     = s * p.x;
            acc[q * 2 + 1] = s * p.y;
        }
    }
    int beg = g_rowptr[d], end = g_rowptr[d + 1];
    int j = beg;
    for (; j + 3 < end; j += 4) {
        int s0 = g_esrc[j], s1 = g_esrc[j + 1], s2 = g_esrc[j + 2], s3 = g_esrc[j + 3];
        float n0 = g_enorm[j], n1 = g_enorm[j + 1], n2 = g_enorm[j + 2], n3 = g_enorm[j + 3];
        uint4 r0 = X[(size_t)s0 * 8 + f];
        uint4 r1 = X[(size_t)s1 * 8 + f];
        uint4 r2 = X[(size_t)s2 * 8 + f];
        uint4 r3 = X[(size_t)s3 * 8 + f];
        fma8(acc, r0, n0); fma8(acc, r1, n1); fma8(acc, r2, n2); fma8(acc, r3, n3);
    }
    for (; j < end; j++) {
        fma8(acc, X[(size_t)g_esrc[j] * 8 + f], g_enorm[j]);
    }
    float4 b0 = b2v[f * 2], b1 = b2v[f * 2 + 1];
    float4 o0, o1;
    o0.x = acc[0] + b0.x; o0.y = acc[1] + b0.y; o0.z = acc[2] + b0.z; o0.w = acc[3] + b0.w;
    o1.x = acc[4] + b1.x; o1.y = acc[5] + b1.y; o1.z = acc[6] + b1.z; o1.w = acc[7] + b1.w;
    out[(size_t)d * 16 + f * 2]     = o0;
    out[(size_t)d * 16 + f * 2 + 1] = o1;
}

// ---------------- launch -----------------------------------------------------
extern "C" void kernel_launch(void* const* d_in, const int* in_sizes, int n_in,
                              void* d_out, int out_size) {
    const float* x  = (const float*)d_in[0];
    const int*   ei = (const int*)  d_in[1];
    const float* ew = (const float*)d_in[2];
    const float* W1 = (const float*)d_in[3];
    const float* b1 = (const float*)d_in[4];
    const float* W2 = (const float*)d_in[5];
    const float* b2 = (const float*)d_in[6];

    void *p_w1h, *p_w2h, *p_w2l, *p_xw1h, *p_h, *p_hw2h;
    cudaGetSymbolAddress(&p_w1h,  g_w1h);
    cudaGetSymbolAddress(&p_w2h,  g_w2h);
    cudaGetSymbolAddress(&p_w2l,  g_w2l);
    cudaGetSymbolAddress(&p_xw1h, g_xw1h);
    cudaGetSymbolAddress(&p_h,    g_h);
    cudaGetSymbolAddress(&p_hw2h, g_hw2h);

    static cudaStream_t s2 = nullptr;
    static cudaEvent_t evFork = nullptr, evJoin = nullptr;
    if (s2 == nullptr) {
        cudaFuncSetAttribute(gemm1_kernel, cudaFuncAttributeMaxDynamicSharedMemorySize,
                             G1_SMEM_BYTES);
        cudaStreamCreateWithFlags(&s2, cudaStreamNonBlocking);
        cudaEventCreateWithFlags(&evFork, cudaEventDisableTiming);
        cudaEventCreateWithFlags(&evJoin, cudaEventDisableTiming);
    }

    // ---- fork: chain B (CSR build) on s2, chain A (weights + GEMM1) on 0 ----
    cudaEventRecord(evFork, 0);
    cudaStreamWaitEvent(s2, evFork, 0);

    z1_kernel  <<<(NN + 255) / 256, 256, 0, s2>>>();
    hist_kernel<<<(NE + 255) / 256, 256, 0, s2>>>(ei, ew);
    dinv_kernel<<<(NN + 255) / 256, 256, 0, s2>>>();
    scan1_kernel<<<NSCAN_BLKS, 1024, 0, s2>>>();
    scan2_kernel<<<1, 128, 0, s2>>>();
    scan3_kernel<<<NSCAN_BLKS, 1024, 0, s2>>>();
    scatter_kernel<<<(NE + 255) / 256, 256, 0, s2>>>(ei, ew);
    cudaEventRecord(evJoin, s2);

    // chain A (stream 0): weight convert -> GEMM1 (x converted in-kernel)
    splitw_kernel<<<(FIN * FH + FH * FO + 255) / 256, 256>>>(W1, W2);
    {
        dim3 grid(FH / 64, NPAD / 128);
        gemm1_kernel<<<grid, 256, G1_SMEM_BYTES>>>(x, (const __half*)p_w1h,
                                                   (__half*)p_xw1h);
    }

    // ---- join: agg1 needs both chains ----
    cudaStreamWaitEvent(0, evJoin, 0);

    {
        dim3 blk(32, 8);
        agg1_kernel<<<(NN + 7) / 8, blk>>>((const float4*)b1);
    }
    {
        dim3 grid(1, NPAD / 128);
        gemm2_kernel<<<grid, 256>>>((const __half*)p_h, (const __half*)p_w2h,
                                    (const __half*)p_w2l, (__half*)p_hw2h);
    }
    {
        dim3 blk(8, 32);
        agg2_kernel<<<(NN + 31) / 32, blk>>>((const float4*)b2, (float4*)d_out);
    }

    (void)in_sizes; (void)n_in; (void)out_size;
}